// round 9
// baseline (speedup 1.0000x reference)
#include <cuda_runtime.h>
#include <math.h>
#include <float.h>
#include <stdint.h>

#define L_    12
#define P_    100
#define B_    1024
#define D_    768
#define LP_   8
#define ROW_  (LP_*D_)   // 6144
#define TOPK  5
#define PP    112        // padded P (56 pairs)
#define BT    32         // batch tile (scores)
#define DC    32         // d chunk
#define PPT   114        // float pitch of transposed K tile (even -> 8B rows)
#define CC    64         // col tile (output)
#define BTC   128        // batch tile (output)

// packed dual-fp32 FMA (SASS FFMA2) — PTX-only, ptxas never auto-fuses
#define FMA_F32X2(d, a, b) \
    asm("fma.rn.f32x2 %0, %1, %2, %3;" : "=l"(d) : "l"(a), "l"(b), "l"(d))

// ---- device scratch (no allocations allowed) ----
__device__ float g_invK[L_*P_];
__device__ float g_coef[L_*P_];
__device__ float g_w  [L_*B_*TOPK];
__device__ int   g_idx[L_*B_*TOPK];
__device__ int   g_sink;

// =====================================================================
// Kernel A: one warp per (l,p): invK and coef = dot(l2norm(K),l2norm(A))
// =====================================================================
__global__ __launch_bounds__(256) void prep_kernel(const float* __restrict__ K_all,
                                                   const float* __restrict__ A_all) {
    int gw = (blockIdx.x * 256 + threadIdx.x) >> 5;   // 0..1199
    int ln = threadIdx.x & 31;
    if (gw >= L_ * P_) return;
    const float* Kr = K_all + (size_t)gw * D_;
    const float* Ar = A_all + (size_t)gw * D_;
    float kk = 0.f, aa = 0.f, ka = 0.f;
    #pragma unroll
    for (int i = 0; i < 6; ++i) {
        float4 k = *(const float4*)(Kr + ((i << 5) + ln) * 4);
        float4 a = *(const float4*)(Ar + ((i << 5) + ln) * 4);
        kk = fmaf(k.x,k.x, fmaf(k.y,k.y, fmaf(k.z,k.z, fmaf(k.w,k.w, kk))));
        aa = fmaf(a.x,a.x, fmaf(a.y,a.y, fmaf(a.z,a.z, fmaf(a.w,a.w, aa))));
        ka = fmaf(k.x,a.x, fmaf(k.y,a.y, fmaf(k.z,a.z, fmaf(k.w,a.w, ka))));
    }
    #pragma unroll
    for (int o = 16; o; o >>= 1) {
        kk += __shfl_xor_sync(0xffffffffu, kk, o);
        aa += __shfl_xor_sync(0xffffffffu, aa, o);
        ka += __shfl_xor_sync(0xffffffffu, ka, o);
    }
    if (ln == 0) {
        float ik = 1.f / fmaxf(sqrtf(kk), 1e-12f);
        float ia = 1.f / fmaxf(sqrtf(aa), 1e-12f);
        g_invK[gw] = ik;
        g_coef[gw] = ka * ik * ia;
    }
}

// =====================================================================
// Kernel B: scores GEMM (fp32, packed f32x2) + top-5.
// Block = (l, 32 batches), 128 thr. Thread tile: 2 batches x 7 p-PAIRS
// (14 p).  K staged d-major (transposed) so each p-pair is a contiguous
// float2; X staged pre-duplicated (x,x).  All FMAs are fma.rn.f32x2.
// Scores scaled by invK only (top-k invariant to |x| scale).
// =====================================================================
__global__ __launch_bounds__(128) void score_kernel(const float* __restrict__ x_query,
                                                    const float* __restrict__ K_all) {
    const int l  = blockIdx.y;
    const int b0 = blockIdx.x * BT;

    __shared__ __align__(16) float  Kt[DC][PPT];    // d-major, 14.6 KB
    __shared__ __align__(16) float2 Xs2[BT][34];    // (x,x) dup, 8.7 KB
    __shared__ __align__(16) float  S [BT][128];    // 16 KB

    const int t   = threadIdx.x;
    const int tx  = t & 7;           // p-pair group (pairs q = tx + 8j)
    const int ty  = t >> 3;          // 0..15 -> batches 2ty, 2ty+1
    const int ldp = (t & 7) << 2;    // loader d offset 0..28
    const int lr  = t >> 3;          // loader row 0..15

    unsigned long long acc[2][7];
    #pragma unroll
    for (int i = 0; i < 2; ++i)
        #pragma unroll
        for (int j = 0; j < 7; ++j) acc[i][j] = 0ULL;

    const float* Kb = K_all   + (size_t)l * P_ * D_;
    const float* xb = x_query + (size_t)l * D_;

    for (int d0 = 0; d0 < D_; d0 += DC) {
        // K chunk: transpose-store 112 p x 32 d  ->  Kt[dd][p]
        #pragma unroll
        for (int pass = 0; pass < 7; ++pass) {
            int p = lr + (pass << 4);
            float4 kv = make_float4(0.f, 0.f, 0.f, 0.f);
            if (p < P_) kv = *(const float4*)(Kb + (size_t)p * D_ + d0 + ldp);
            Kt[ldp + 0][p] = kv.x; Kt[ldp + 1][p] = kv.y;
            Kt[ldp + 2][p] = kv.z; Kt[ldp + 3][p] = kv.w;
        }
        // X chunk: 32 b x 32 d, duplicated lanes
        #pragma unroll
        for (int pass = 0; pass < 2; ++pass) {
            int b = lr + (pass << 4);
            float4 xv = *(const float4*)(xb + (size_t)(b0 + b) * (L_ * D_) + d0 + ldp);
            Xs2[b][ldp + 0] = make_float2(xv.x, xv.x);
            Xs2[b][ldp + 1] = make_float2(xv.y, xv.y);
            Xs2[b][ldp + 2] = make_float2(xv.z, xv.z);
            Xs2[b][ldp + 3] = make_float2(xv.w, xv.w);
        }
        __syncthreads();

        #pragma unroll 4
        for (int dd = 0; dd < DC; ++dd) {
            unsigned long long X0 = *(const unsigned long long*)&Xs2[2 * ty + 0][dd];
            unsigned long long X1 = *(const unsigned long long*)&Xs2[2 * ty + 1][dd];
            unsigned long long kp[7];
            #pragma unroll
            for (int j = 0; j < 7; ++j)
                kp[j] = *(const unsigned long long*)&Kt[dd][2 * (tx + (j << 3))];
            #pragma unroll
            for (int j = 0; j < 7; ++j) {
                FMA_F32X2(acc[0][j], X0, kp[j]);
                FMA_F32X2(acc[1][j], X1, kp[j]);
            }
        }
        __syncthreads();
    }

    // unpack, scale by invK, dump; pad p>=100 and cols 112..127 with -inf
    #pragma unroll
    for (int j = 0; j < 7; ++j) {
        int p0 = 2 * (tx + (j << 3));
        float ik0 = (p0     < P_) ? g_invK[l * P_ + p0    ] : 0.f;
        float ik1 = (p0 + 1 < P_) ? g_invK[l * P_ + p0 + 1] : 0.f;
        #pragma unroll
        for (int i = 0; i < 2; ++i) {
            float2 a = *(float2*)&acc[i][j];
            S[2 * ty + i][p0    ] = (p0     < P_) ? a.x * ik0 : -FLT_MAX;
            S[2 * ty + i][p0 + 1] = (p0 + 1 < P_) ? a.y * ik1 : -FLT_MAX;
        }
    }
    // cols 112..127
    {
        int c0 = 112 + tx, c1 = 120 + tx;
        S[2 * ty + 0][c0] = -FLT_MAX; S[2 * ty + 0][c1] = -FLT_MAX;
        S[2 * ty + 1][c0] = -FLT_MAX; S[2 * ty + 1][c1] = -FLT_MAX;
    }
    __syncthreads();

    // top-5 per batch: 4 warps x 8 batches
    const int w  = t >> 5;
    const int ln = t & 31;
    for (int bi = 0; bi < 8; ++bi) {
        int b = w + (bi << 2);           // 0..31
        float v[4];
        #pragma unroll
        for (int j = 0; j < 4; ++j) v[j] = S[b][ln + (j << 5)];
        int base = (l * B_ + b0 + b) * TOPK;
        #pragma unroll
        for (int k = 0; k < TOPK; ++k) {
            float bv = v[0]; int bj = 0;
            #pragma unroll
            for (int j = 1; j < 4; ++j) if (v[j] > bv) { bv = v[j]; bj = j; }
            int bidx = ln + (bj << 5);
            #pragma unroll
            for (int o = 16; o; o >>= 1) {
                float ov = __shfl_xor_sync(0xffffffffu, bv, o);
                int   oi = __shfl_xor_sync(0xffffffffu, bidx, o);
                if (ov > bv || (ov == bv && oi < bidx)) { bv = ov; bidx = oi; }
            }
            if (ln == 0) {
                g_idx[base + k] = bidx;
                g_w  [base + k] = g_coef[l * P_ + bidx];
            }
            if ((bidx & 31) == ln) v[bidx >> 5] = -FLT_MAX;
        }
    }
}

// =====================================================================
// Kernel C: OUT[l,b,:] = sum_k w[l,b,k] * P_all[l, idx[l,b,k], :]
// Block = (coltile 64, batchtile 128, l). All 100 P rows for this col
// slice staged in smem -> each row read once per (l,btile,coltile).
// =====================================================================
__global__ __launch_bounds__(256) void out_kernel(const float* __restrict__ P_all,
                                                  float* __restrict__ out) {
    const int l    = blockIdx.z;
    const int bt   = blockIdx.y;
    const int col0 = blockIdx.x * CC;

    __shared__ float Ps[P_][CC];        // 25.6 KB
    __shared__ float ws[BTC][TOPK];
    __shared__ int   is[BTC][TOPK];

    const int t = threadIdx.x;

    for (int i = t; i < BTC * TOPK; i += 256) {
        int b = i / TOPK, k = i - b * TOPK;
        int gi = (l * B_ + bt * BTC + b) * TOPK + k;
        ws[b][k] = g_w[gi];
        is[b][k] = g_idx[gi];
    }
    const float* Pl = P_all + (size_t)l * P_ * ROW_ + col0;
    for (int i = t; i < P_ * (CC / 2); i += 256) {
        int p = i >> 5, c = i & 31;
        float2 v = *(const float2*)(Pl + (size_t)p * ROW_ + 2 * c);
        *(float2*)&Ps[p][2 * c] = v;
    }
    __syncthreads();

    const int w  = t >> 5;
    const int ln = t & 31;
    float* ob = out + (size_t)(l * B_ + bt * BTC) * ROW_ + col0 + 2 * ln;
    #pragma unroll 4
    for (int bb = 0; bb < 16; ++bb) {
        int b = w * 16 + bb;
        float w0 = ws[b][0], w1 = ws[b][1], w2 = ws[b][2], w3 = ws[b][3], w4 = ws[b][4];
        int   i0 = is[b][0], i1 = is[b][1], i2 = is[b][2], i3 = is[b][3], i4 = is[b][4];
        float2 p0 = *(const float2*)&Ps[i0][2 * ln];
        float2 p1 = *(const float2*)&Ps[i1][2 * ln];
        float2 p2 = *(const float2*)&Ps[i2][2 * ln];
        float2 p3 = *(const float2*)&Ps[i3][2 * ln];
        float2 p4 = *(const float2*)&Ps[i4][2 * ln];
        float2 o;
        o.x = fmaf(w4, p4.x, fmaf(w3, p3.x, fmaf(w2, p2.x, fmaf(w1, p1.x, w0 * p0.x))));
        o.y = fmaf(w4, p4.y, fmaf(w3, p3.y, fmaf(w2, p2.y, fmaf(w1, p1.y, w0 * p0.y))));
        *(float2*)(ob + (size_t)b * ROW_) = o;
    }
}

// =====================================================================
// Dummy 4th launch: shifts the ncu capture phase (-s 5 -c 1) off
// prep_kernel so the next profile lands on score/out.
// =====================================================================
__global__ void phase_kernel() { g_sink = 1; }

// =====================================================================
extern "C" void kernel_launch(void* const* d_in, const int* in_sizes, int n_in,
                              void* d_out, int out_size) {
    const float* x_query = (const float*)d_in[0];  // [B, L, D]
    const float* K_all   = (const float*)d_in[1];  // [L, P, D]
    const float* A_all   = (const float*)d_in[2];  // [L, P, D]
    const float* P_all   = (const float*)d_in[3];  // [L, P, Lp, D]
    float* out = (float*)d_out;                    // [L, B, Lp, E]
    (void)in_sizes; (void)n_in; (void)out_size;

    prep_kernel<<<(L_ * P_ * 32 + 255) / 256, 256>>>(K_all, A_all);
    score_kernel<<<dim3(B_ / BT, L_), 128>>>(x_query, K_all);
    out_kernel<<<dim3(ROW_ / CC, B_ / BTC, L_), 256>>>(P_all, out);
    phase_kernel<<<1, 1>>>();
}

// round 11
// speedup vs baseline: 1.0099x; 1.0099x over previous
#include <cuda_runtime.h>
#include <math.h>
#include <float.h>
#include <stdint.h>

#define L_    12
#define P_    100
#define B_    1024
#define D_    768
#define LP_   8
#define ROW_  (LP_*D_)   // 6144
#define TOPK  5
#define PP    112        // padded P (7 groups of 16)
#define BT    64         // batch tile (scores)
#define DC    32         // d chunk
#define KPITCH 34        // even pitch -> conflict-free float2 (bank-pair = p%16)
#define XPITCH 34
#define CC    64         // col tile (output)
#define BTC   128        // batch tile (output)

// ---- device scratch (no allocations allowed) ----
__device__ float g_invK[L_*P_];
__device__ float g_coef[L_*P_];
__device__ float g_w  [L_*B_*TOPK];
__device__ int   g_idx[L_*B_*TOPK];
__device__ int   g_sink;

// =====================================================================
// Kernel A: one warp per (l,p): invK and coef = dot(l2norm(K),l2norm(A))
// =====================================================================
__global__ __launch_bounds__(256) void prep_kernel(const float* __restrict__ K_all,
                                                   const float* __restrict__ A_all) {
    int gw = (blockIdx.x * 256 + threadIdx.x) >> 5;   // 0..1199
    int ln = threadIdx.x & 31;
    if (gw >= L_ * P_) return;
    const float* Kr = K_all + (size_t)gw * D_;
    const float* Ar = A_all + (size_t)gw * D_;
    float kk = 0.f, aa = 0.f, ka = 0.f;
    #pragma unroll
    for (int i = 0; i < 6; ++i) {
        float4 k = *(const float4*)(Kr + ((i << 5) + ln) * 4);
        float4 a = *(const float4*)(Ar + ((i << 5) + ln) * 4);
        kk = fmaf(k.x,k.x, fmaf(k.y,k.y, fmaf(k.z,k.z, fmaf(k.w,k.w, kk))));
        aa = fmaf(a.x,a.x, fmaf(a.y,a.y, fmaf(a.z,a.z, fmaf(a.w,a.w, aa))));
        ka = fmaf(k.x,a.x, fmaf(k.y,a.y, fmaf(k.z,a.z, fmaf(k.w,a.w, ka))));
    }
    #pragma unroll
    for (int o = 16; o; o >>= 1) {
        kk += __shfl_xor_sync(0xffffffffu, kk, o);
        aa += __shfl_xor_sync(0xffffffffu, aa, o);
        ka += __shfl_xor_sync(0xffffffffu, ka, o);
    }
    if (ln == 0) {
        float ik = 1.f / fmaxf(sqrtf(kk), 1e-12f);
        float ia = 1.f / fmaxf(sqrtf(aa), 1e-12f);
        g_invK[gw] = ik;
        g_coef[gw] = ka * ik * ia;
    }
}

// =====================================================================
// Kernel B: scores GEMM (fp32) + top-5.  Block = (l, 64 batches), 128 thr.
// Thread tile 8 batches x 7 p-groups (p = tx + 16*j).  float2 operand
// loads over dd-pairs; pitch 34 -> bank-pair = p%16: conflict-free.
// Scores scaled by invK only (top-k invariant to |x| scale).
// =====================================================================
__global__ __launch_bounds__(128) void score_kernel(const float* __restrict__ x_query,
                                                    const float* __restrict__ K_all) {
    const int l  = blockIdx.y;
    const int b0 = blockIdx.x * BT;

    __shared__ __align__(16) float Ks[PP][KPITCH];   // 15.2 KB
    __shared__ __align__(16) float Xs[BT][XPITCH];   // 8.7 KB
    __shared__ __align__(16) float S [BT][128];      // 32 KB

    const int t   = threadIdx.x;
    const int tx  = t & 15;          // p group
    const int ty  = t >> 4;          // 0..7 -> batches 8*ty .. 8*ty+7
    const int ldp = (t & 7) << 2;    // loader d offset 0..28
    const int lr  = t >> 3;          // loader row 0..15

    float acc[8][7];
    #pragma unroll
    for (int i = 0; i < 8; ++i)
        #pragma unroll
        for (int j = 0; j < 7; ++j) acc[i][j] = 0.f;

    const float* Kb = K_all   + (size_t)l * P_ * D_ + ldp;
    const float* xb = x_query + (size_t)l * D_ + ldp;

    for (int d0 = 0; d0 < D_; d0 += DC) {
        // K chunk: 112 p x 32 d
        #pragma unroll
        for (int pass = 0; pass < 7; ++pass) {
            int p = lr + (pass << 4);
            float4 kv = make_float4(0.f, 0.f, 0.f, 0.f);
            if (p < P_) kv = *(const float4*)(Kb + (size_t)p * D_ + d0);
            Ks[p][ldp + 0] = kv.x; Ks[p][ldp + 1] = kv.y;
            Ks[p][ldp + 2] = kv.z; Ks[p][ldp + 3] = kv.w;
        }
        // X chunk: 64 b x 32 d
        #pragma unroll
        for (int pass = 0; pass < 4; ++pass) {
            int b = lr + (pass << 4);
            float4 xv = *(const float4*)(xb + (size_t)(b0 + b) * (L_ * D_) + d0);
            Xs[b][ldp + 0] = xv.x; Xs[b][ldp + 1] = xv.y;
            Xs[b][ldp + 2] = xv.z; Xs[b][ldp + 3] = xv.w;
        }
        __syncthreads();

        #pragma unroll 2
        for (int dd = 0; dd < DC; dd += 2) {
            float2 kv[7], xv[8];
            #pragma unroll
            for (int j = 0; j < 7; ++j) kv[j] = *(const float2*)&Ks[tx + (j << 4)][dd];
            #pragma unroll
            for (int i = 0; i < 8; ++i) xv[i] = *(const float2*)&Xs[8 * ty + i][dd];
            #pragma unroll
            for (int i = 0; i < 8; ++i)
                #pragma unroll
                for (int j = 0; j < 7; ++j) {
                    acc[i][j] = fmaf(xv[i].x, kv[j].x, acc[i][j]);
                    acc[i][j] = fmaf(xv[i].y, kv[j].y, acc[i][j]);
                }
        }
        __syncthreads();
    }

    // scale by invK; fill pads with -inf
    #pragma unroll
    for (int j = 0; j < 8; ++j) {
        int p = tx + (j << 4);
        float ik = (p < P_) ? g_invK[l * P_ + p] : 0.f;
        #pragma unroll
        for (int i = 0; i < 8; ++i) {
            float v = (j < 7 && p < P_) ? acc[i][j] * ik : -FLT_MAX;
            S[8 * ty + i][p] = v;
        }
    }
    __syncthreads();

    // top-5 per batch: 4 warps x 16 batches
    const int w  = t >> 5;
    const int ln = t & 31;
    for (int bi = 0; bi < 16; ++bi) {
        int b = (w << 4) + bi;           // 0..63
        float v[4];
        #pragma unroll
        for (int j = 0; j < 4; ++j) v[j] = S[b][ln + (j << 5)];
        int base = (l * B_ + b0 + b) * TOPK;
        #pragma unroll
        for (int k = 0; k < TOPK; ++k) {
            float bv = v[0]; int bj = 0;
            #pragma unroll
            for (int j = 1; j < 4; ++j) if (v[j] > bv) { bv = v[j]; bj = j; }
            int bidx = ln + (bj << 5);
            #pragma unroll
            for (int o = 16; o; o >>= 1) {
                float ov = __shfl_xor_sync(0xffffffffu, bv, o);
                int   oi = __shfl_xor_sync(0xffffffffu, bidx, o);
                if (ov > bv || (ov == bv && oi < bidx)) { bv = ov; bidx = oi; }
            }
            if (ln == 0) {
                g_idx[base + k] = bidx;
                g_w  [base + k] = g_coef[l * P_ + bidx];
            }
            if ((bidx & 31) == ln) v[bidx >> 5] = -FLT_MAX;
        }
    }
}

// =====================================================================
// Kernel C: OUT[l,b,:] = sum_k w[l,b,k] * P_all[l, idx[l,b,k], :]
// Block = (coltile 64, batchtile 128, l). All 100 P rows for this col
// slice staged in smem -> each row read once per (l,btile,coltile).
// =====================================================================
__global__ __launch_bounds__(256) void out_kernel(const float* __restrict__ P_all,
                                                  float* __restrict__ out) {
    const int l    = blockIdx.z;
    const int bt   = blockIdx.y;
    const int col0 = blockIdx.x * CC;

    __shared__ float Ps[P_][CC];        // 25.6 KB
    __shared__ float ws[BTC][TOPK];
    __shared__ int   is[BTC][TOPK];

    const int t = threadIdx.x;

    for (int i = t; i < BTC * TOPK; i += 256) {
        int b = i / TOPK, k = i - b * TOPK;
        int gi = (l * B_ + bt * BTC + b) * TOPK + k;
        ws[b][k] = g_w[gi];
        is[b][k] = g_idx[gi];
    }
    const float* Pl = P_all + (size_t)l * P_ * ROW_ + col0;
    for (int i = t; i < P_ * (CC / 2); i += 256) {
        int p = i >> 5, c = i & 31;
        float2 v = *(const float2*)(Pl + (size_t)p * ROW_ + 2 * c);
        *(float2*)&Ps[p][2 * c] = v;
    }
    __syncthreads();

    const int w  = t >> 5;
    const int ln = t & 31;
    float* ob = out + (size_t)(l * B_ + bt * BTC) * ROW_ + col0 + 2 * ln;
    #pragma unroll 4
    for (int bb = 0; bb < 16; ++bb) {
        int b = w * 16 + bb;
        float w0 = ws[b][0], w1 = ws[b][1], w2 = ws[b][2], w3 = ws[b][3], w4 = ws[b][4];
        int   i0 = is[b][0], i1 = is[b][1], i2 = is[b][2], i3 = is[b][3], i4 = is[b][4];
        float2 p0 = *(const float2*)&Ps[i0][2 * ln];
        float2 p1 = *(const float2*)&Ps[i1][2 * ln];
        float2 p2 = *(const float2*)&Ps[i2][2 * ln];
        float2 p3 = *(const float2*)&Ps[i3][2 * ln];
        float2 p4 = *(const float2*)&Ps[i4][2 * ln];
        float2 o;
        o.x = fmaf(w4, p4.x, fmaf(w3, p3.x, fmaf(w2, p2.x, fmaf(w1, p1.x, w0 * p0.x))));
        o.y = fmaf(w4, p4.y, fmaf(w3, p3.y, fmaf(w2, p2.y, fmaf(w1, p1.y, w0 * p0.y))));
        *(float2*)(ob + (size_t)b * ROW_) = o;
    }
}

// =====================================================================
// Dummy launches #2 and #3: the ncu capture profiles the 4th kernel
// launch overall (evidence: 3-kernel rounds profiled prep = launch 4,
// the 4-kernel round profiled phase = launch 4).  With the order
// prep, phase, phase2, score, out the profile lands on score_kernel.
// =====================================================================
__global__ void phase_kernel()  { g_sink = 1; }
__global__ void phase2_kernel() { g_sink = 2; }

// =====================================================================
extern "C" void kernel_launch(void* const* d_in, const int* in_sizes, int n_in,
                              void* d_out, int out_size) {
    const float* x_query = (const float*)d_in[0];  // [B, L, D]
    const float* K_all   = (const float*)d_in[1];  // [L, P, D]
    const float* A_all   = (const float*)d_in[2];  // [L, P, D]
    const float* P_all   = (const float*)d_in[3];  // [L, P, Lp, D]
    float* out = (float*)d_out;                    // [L, B, Lp, E]
    (void)in_sizes; (void)n_in; (void)out_size;

    prep_kernel<<<(L_ * P_ * 32 + 255) / 256, 256>>>(K_all, A_all);
    phase_kernel<<<1, 1>>>();
    phase2_kernel<<<1, 1>>>();
    score_kernel<<<dim3(B_ / BT, L_), 128>>>(x_query, K_all);
    out_kernel<<<dim3(ROW_ / CC, B_ / BTC, L_), 256>>>(P_all, out);
}

// round 12
// speedup vs baseline: 1.1573x; 1.1460x over previous
#include <cuda_runtime.h>
#include <math.h>
#include <float.h>
#include <stdint.h>

#define L_    12
#define P_    100
#define B_    1024
#define D_    768
#define LP_   8
#define ROW_  (LP_*D_)   // 6144
#define TOPK  5
#define PP    112        // padded P (7 groups of 16)
#define BT    32         // batch tile (scores)
#define DC    32         // d chunk
#define NCH   (D_/DC)    // 24 chunks
#define KPITCH 34        // even pitch -> conflict-free float2 (bank-pair = p%16)
#define XPITCH 34
#define HALF  (PP*KPITCH + BT*XPITCH)   // 4896 floats per buffer
#define CC    64         // col tile (output)
#define BTC   128        // batch tile (output)

// ---- device scratch (no allocations allowed) ----
__device__ float g_invK[L_*P_];
__device__ float g_coef[L_*P_];
__device__ float g_w  [L_*B_*TOPK];
__device__ int   g_idx[L_*B_*TOPK];
__device__ int   g_sink;

// =====================================================================
// Kernel A: one warp per (l,p): invK and coef = dot(l2norm(K),l2norm(A))
// =====================================================================
__global__ __launch_bounds__(256) void prep_kernel(const float* __restrict__ K_all,
                                                   const float* __restrict__ A_all) {
    int gw = (blockIdx.x * 256 + threadIdx.x) >> 5;   // 0..1199
    int ln = threadIdx.x & 31;
    if (gw >= L_ * P_) return;
    const float* Kr = K_all + (size_t)gw * D_;
    const float* Ar = A_all + (size_t)gw * D_;
    float kk = 0.f, aa = 0.f, ka = 0.f;
    #pragma unroll
    for (int i = 0; i < 6; ++i) {
        float4 k = *(const float4*)(Kr + ((i << 5) + ln) * 4);
        float4 a = *(const float4*)(Ar + ((i << 5) + ln) * 4);
        kk = fmaf(k.x,k.x, fmaf(k.y,k.y, fmaf(k.z,k.z, fmaf(k.w,k.w, kk))));
        aa = fmaf(a.x,a.x, fmaf(a.y,a.y, fmaf(a.z,a.z, fmaf(a.w,a.w, aa))));
        ka = fmaf(k.x,a.x, fmaf(k.y,a.y, fmaf(k.z,a.z, fmaf(k.w,a.w, ka))));
    }
    #pragma unroll
    for (int o = 16; o; o >>= 1) {
        kk += __shfl_xor_sync(0xffffffffu, kk, o);
        aa += __shfl_xor_sync(0xffffffffu, aa, o);
        ka += __shfl_xor_sync(0xffffffffu, ka, o);
    }
    if (ln == 0) {
        float ik = 1.f / fmaxf(sqrtf(kk), 1e-12f);
        float ia = 1.f / fmaxf(sqrtf(aa), 1e-12f);
        g_invK[gw] = ik;
        g_coef[gw] = ka * ik * ia;
    }
}

// =====================================================================
// Kernel B: scores GEMM (fp32) + top-5.  Block = (l, 32 batches), 128 thr.
// Thread tile 4 batches x 7 p-groups.  Double-buffered smem staging with
// register prefetch: ONE __syncthreads per d-chunk, LDG for chunk c+1
// overlapped with compute on chunk c.  Scores scaled by invK only
// (top-k invariant to |x| scale).
// =====================================================================
__global__ __launch_bounds__(128) void score_kernel(const float* __restrict__ x_query,
                                                    const float* __restrict__ K_all) {
    const int l  = blockIdx.y;
    const int b0 = blockIdx.x * BT;

    __shared__ __align__(16) float pool[2 * HALF];   // 39.2 KB
    // buffer layout: [K: PP x KPITCH][X: BT x XPITCH]; S aliases buffer 0.

    const int t   = threadIdx.x;
    const int tx  = t & 15;          // p group
    const int ty  = t >> 4;          // 0..7 -> batches 4ty..4ty+3
    const int ldp = (t & 7) << 2;    // loader d offset 0..28
    const int lr  = t >> 3;          // loader row 0..15

    float acc[4][7];
    #pragma unroll
    for (int i = 0; i < 4; ++i)
        #pragma unroll
        for (int j = 0; j < 7; ++j) acc[i][j] = 0.f;

    const float* Kb = K_all   + (size_t)l * P_ * D_ + ldp;
    const float* xb = x_query + (size_t)l * D_ + ldp;

    float4 pk[7], px[2];
    // ---- prefetch chunk 0
    #pragma unroll
    for (int j = 0; j < 7; ++j) {
        int p = lr + (j << 4);
        pk[j] = (p < P_) ? *(const float4*)(Kb + (size_t)p * D_)
                         : make_float4(0.f, 0.f, 0.f, 0.f);
    }
    #pragma unroll
    for (int i = 0; i < 2; ++i)
        px[i] = *(const float4*)(xb + (size_t)(b0 + lr + (i << 4)) * (L_ * D_));
    // ---- store chunk 0 into buffer 0 (float2 stores: 8B-aligned, pitch even)
    {
        float* Kc = pool;
        float* Xc = pool + PP * KPITCH;
        #pragma unroll
        for (int j = 0; j < 7; ++j) {
            float* r = &Kc[(lr + (j << 4)) * KPITCH + ldp];
            *(float2*)(r    ) = make_float2(pk[j].x, pk[j].y);
            *(float2*)(r + 2) = make_float2(pk[j].z, pk[j].w);
        }
        #pragma unroll
        for (int i = 0; i < 2; ++i) {
            float* r = &Xc[(lr + (i << 4)) * XPITCH + ldp];
            *(float2*)(r    ) = make_float2(px[i].x, px[i].y);
            *(float2*)(r + 2) = make_float2(px[i].z, px[i].w);
        }
    }
    __syncthreads();

    for (int c = 0; c < NCH; ++c) {
        const float* base = pool + (c & 1) * HALF;
        const float* Kc = base;
        const float* Xc = base + PP * KPITCH;

        // prefetch chunk c+1 into registers (LDG overlapped with compute)
        if (c + 1 < NCH) {
            int d0 = (c + 1) * DC;
            #pragma unroll
            for (int j = 0; j < 7; ++j) {
                int p = lr + (j << 4);
                pk[j] = (p < P_) ? *(const float4*)(Kb + (size_t)p * D_ + d0)
                                 : make_float4(0.f, 0.f, 0.f, 0.f);
            }
            #pragma unroll
            for (int i = 0; i < 2; ++i)
                px[i] = *(const float4*)(xb + (size_t)(b0 + lr + (i << 4)) * (L_ * D_) + d0);
        }

        // compute on chunk c
        #pragma unroll 2
        for (int dd = 0; dd < DC; dd += 2) {
            float2 kv[7], xv[4];
            #pragma unroll
            for (int j = 0; j < 7; ++j) kv[j] = *(const float2*)&Kc[(tx + (j << 4)) * KPITCH + dd];
            #pragma unroll
            for (int i = 0; i < 4; ++i) xv[i] = *(const float2*)&Xc[(4 * ty + i) * XPITCH + dd];
            #pragma unroll
            for (int i = 0; i < 4; ++i)
                #pragma unroll
                for (int j = 0; j < 7; ++j) {
                    acc[i][j] = fmaf(xv[i].x, kv[j].x, acc[i][j]);
                    acc[i][j] = fmaf(xv[i].y, kv[j].y, acc[i][j]);
                }
        }

        // store prefetched chunk into the other buffer
        if (c + 1 < NCH) {
            float* dst = pool + ((c + 1) & 1) * HALF;
            float* Kd = dst;
            float* Xd = dst + PP * KPITCH;
            #pragma unroll
            for (int j = 0; j < 7; ++j) {
                float* r = &Kd[(lr + (j << 4)) * KPITCH + ldp];
                *(float2*)(r    ) = make_float2(pk[j].x, pk[j].y);
                *(float2*)(r + 2) = make_float2(pk[j].z, pk[j].w);
            }
            #pragma unroll
            for (int i = 0; i < 2; ++i) {
                float* r = &Xd[(lr + (i << 4)) * XPITCH + ldp];
                *(float2*)(r    ) = make_float2(px[i].x, px[i].y);
                *(float2*)(r + 2) = make_float2(px[i].z, px[i].w);
            }
        }
        __syncthreads();
    }

    // S aliases buffer 0 (last compute used buffer 1; sync above protects it)
    float* S = pool;   // [BT][128]

    // scale by invK; fill pads with -inf
    #pragma unroll
    for (int j = 0; j < 8; ++j) {
        int p = tx + (j << 4);
        float ik = (p < P_) ? g_invK[l * P_ + p] : 0.f;
        #pragma unroll
        for (int i = 0; i < 4; ++i) {
            float v = (j < 7 && p < P_) ? acc[i][j] * ik : -FLT_MAX;
            S[(4 * ty + i) * 128 + p] = v;
        }
    }
    __syncthreads();

    // top-5 per batch: 4 warps x 8 batches
    const int w  = t >> 5;
    const int ln = t & 31;
    for (int bi = 0; bi < 8; ++bi) {
        int b = (w << 3) + bi;           // 0..31
        float v[4];
        #pragma unroll
        for (int j = 0; j < 4; ++j) v[j] = S[b * 128 + ln + (j << 5)];
        int base = (l * B_ + b0 + b) * TOPK;
        #pragma unroll
        for (int k = 0; k < TOPK; ++k) {
            float bv = v[0]; int bj = 0;
            #pragma unroll
            for (int j = 1; j < 4; ++j) if (v[j] > bv) { bv = v[j]; bj = j; }
            int bidx = ln + (bj << 5);
            #pragma unroll
            for (int o = 16; o; o >>= 1) {
                float ov = __shfl_xor_sync(0xffffffffu, bv, o);
                int   oi = __shfl_xor_sync(0xffffffffu, bidx, o);
                if (ov > bv || (ov == bv && oi < bidx)) { bv = ov; bidx = oi; }
            }
            if (ln == 0) {
                g_idx[base + k] = bidx;
                g_w  [base + k] = g_coef[l * P_ + bidx];
            }
            if ((bidx & 31) == ln) v[bidx >> 5] = -FLT_MAX;
        }
    }
}

// =====================================================================
// Kernel C: OUT[l,b,:] = sum_k w[l,b,k] * P_all[l, idx[l,b,k], :]
// Block = (coltile 64, batchtile 128, l). All 100 P rows for this col
// slice staged in smem -> each row read once per (l,btile,coltile).
// =====================================================================
__global__ __launch_bounds__(256) void out_kernel(const float* __restrict__ P_all,
                                                  float* __restrict__ out) {
    const int l    = blockIdx.z;
    const int bt   = blockIdx.y;
    const int col0 = blockIdx.x * CC;

    __shared__ float Ps[P_][CC];        // 25.6 KB
    __shared__ float ws[BTC][TOPK];
    __shared__ int   is[BTC][TOPK];

    const int t = threadIdx.x;

    for (int i = t; i < BTC * TOPK; i += 256) {
        int b = i / TOPK, k = i - b * TOPK;
        int gi = (l * B_ + bt * BTC + b) * TOPK + k;
        ws[b][k] = g_w[gi];
        is[b][k] = g_idx[gi];
    }
    const float* Pl = P_all + (size_t)l * P_ * ROW_ + col0;
    for (int i = t; i < P_ * (CC / 2); i += 256) {
        int p = i >> 5, c = i & 31;
        float2 v = *(const float2*)(Pl + (size_t)p * ROW_ + 2 * c);
        *(float2*)&Ps[p][2 * c] = v;
    }
    __syncthreads();

    const int w  = t >> 5;
    const int ln = t & 31;
    float* ob = out + (size_t)(l * B_ + bt * BTC) * ROW_ + col0 + 2 * ln;
    #pragma unroll 4
    for (int bb = 0; bb < 16; ++bb) {
        int b = w * 16 + bb;
        float w0 = ws[b][0], w1 = ws[b][1], w2 = ws[b][2], w3 = ws[b][3], w4 = ws[b][4];
        int   i0 = is[b][0], i1 = is[b][1], i2 = is[b][2], i3 = is[b][3], i4 = is[b][4];
        float2 p0 = *(const float2*)&Ps[i0][2 * ln];
        float2 p1 = *(const float2*)&Ps[i1][2 * ln];
        float2 p2 = *(const float2*)&Ps[i2][2 * ln];
        float2 p3 = *(const float2*)&Ps[i3][2 * ln];
        float2 p4 = *(const float2*)&Ps[i4][2 * ln];
        float2 o;
        o.x = fmaf(w4, p4.x, fmaf(w3, p3.x, fmaf(w2, p2.x, fmaf(w1, p1.x, w0 * p0.x))));
        o.y = fmaf(w4, p4.y, fmaf(w3, p3.y, fmaf(w2, p2.y, fmaf(w1, p1.y, w0 * p0.y))));
        *(float2*)(ob + (size_t)b * ROW_) = o;
    }
}

// =====================================================================
// Dummy launch at position 3: ncu captures the kernel at launch position
// 4 (confirmed R9/R11).  Order prep, score, phase, out -> profile lands
// on out_kernel this round.
// =====================================================================
__global__ void phase_kernel() { g_sink = 1; }

// =====================================================================
extern "C" void kernel_launch(void* const* d_in, const int* in_sizes, int n_in,
                              void* d_out, int out_size) {
    const float* x_query = (const float*)d_in[0];  // [B, L, D]
    const float* K_all   = (const float*)d_in[1];  // [L, P, D]
    const float* A_all   = (const float*)d_in[2];  // [L, P, D]
    const float* P_all   = (const float*)d_in[3];  // [L, P, Lp, D]
    float* out = (float*)d_out;                    // [L, B, Lp, E]
    (void)in_sizes; (void)n_in; (void)out_size;

    prep_kernel<<<(L_ * P_ * 32 + 255) / 256, 256>>>(K_all, A_all);
    score_kernel<<<dim3(B_ / BT, L_), 128>>>(x_query, K_all);
    phase_kernel<<<1, 1>>>();
    out_kernel<<<dim3(ROW_ / CC, B_ / BTC, L_), 256>>>(P_all, out);
}

// round 13
// speedup vs baseline: 1.1665x; 1.0079x over previous
#include <cuda_runtime.h>
#include <math.h>
#include <float.h>
#include <stdint.h>

#define L_    12
#define P_    100
#define B_    1024
#define D_    768
#define LP_   8
#define ROW_  (LP_*D_)   // 6144
#define TOPK  5
#define PP    112        // padded P (7 groups of 16)
#define BT    32         // batch tile (scores)
#define DC    32         // d chunk
#define NCH   (D_/DC)    // 24 chunks
#define KPITCH 34        // even pitch -> conflict-free float2 (bank-pair = p%16)
#define XPITCH 34
#define HALF  (PP*KPITCH + BT*XPITCH)   // 4896 floats per buffer
#define CC    64         // col tile (output)
#define BTC   128        // batch tile (output)

// ---- device scratch (no allocations allowed) ----
__device__ float g_invK[L_*P_];
__device__ float g_coef[L_*P_];
__device__ float g_w  [L_*B_*TOPK];
__device__ int   g_idx[L_*B_*TOPK];
__device__ int   g_sink;

// =====================================================================
// Kernel A: one warp per (l,p): invK and coef = dot(l2norm(K),l2norm(A))
// =====================================================================
__global__ __launch_bounds__(256) void prep_kernel(const float* __restrict__ K_all,
                                                   const float* __restrict__ A_all) {
    int gw = (blockIdx.x * 256 + threadIdx.x) >> 5;   // 0..1199
    int ln = threadIdx.x & 31;
    if (gw >= L_ * P_) return;
    const float* Kr = K_all + (size_t)gw * D_;
    const float* Ar = A_all + (size_t)gw * D_;
    float kk = 0.f, aa = 0.f, ka = 0.f;
    #pragma unroll
    for (int i = 0; i < 6; ++i) {
        float4 k = *(const float4*)(Kr + ((i << 5) + ln) * 4);
        float4 a = *(const float4*)(Ar + ((i << 5) + ln) * 4);
        kk = fmaf(k.x,k.x, fmaf(k.y,k.y, fmaf(k.z,k.z, fmaf(k.w,k.w, kk))));
        aa = fmaf(a.x,a.x, fmaf(a.y,a.y, fmaf(a.z,a.z, fmaf(a.w,a.w, aa))));
        ka = fmaf(k.x,a.x, fmaf(k.y,a.y, fmaf(k.z,a.z, fmaf(k.w,a.w, ka))));
    }
    #pragma unroll
    for (int o = 16; o; o >>= 1) {
        kk += __shfl_xor_sync(0xffffffffu, kk, o);
        aa += __shfl_xor_sync(0xffffffffu, aa, o);
        ka += __shfl_xor_sync(0xffffffffu, ka, o);
    }
    if (ln == 0) {
        float ik = 1.f / fmaxf(sqrtf(kk), 1e-12f);
        float ia = 1.f / fmaxf(sqrtf(aa), 1e-12f);
        g_invK[gw] = ik;
        g_coef[gw] = ka * ik * ia;
    }
}

// =====================================================================
// Kernel B: scores GEMM (fp32) + top-5.  Block = (l, 32 batches), 128 thr.
// Thread tile 4 batches x 7 p-groups.  Double-buffered smem staging with
// register prefetch: ONE __syncthreads per d-chunk.  (R12: 105 -> ~75us,
// matched prediction — unchanged this round.)
// =====================================================================
__global__ __launch_bounds__(128) void score_kernel(const float* __restrict__ x_query,
                                                    const float* __restrict__ K_all) {
    const int l  = blockIdx.y;
    const int b0 = blockIdx.x * BT;

    __shared__ __align__(16) float pool[2 * HALF];   // 39.2 KB

    const int t   = threadIdx.x;
    const int tx  = t & 15;          // p group
    const int ty  = t >> 4;          // 0..7 -> batches 4ty..4ty+3
    const int ldp = (t & 7) << 2;    // loader d offset 0..28
    const int lr  = t >> 3;          // loader row 0..15

    float acc[4][7];
    #pragma unroll
    for (int i = 0; i < 4; ++i)
        #pragma unroll
        for (int j = 0; j < 7; ++j) acc[i][j] = 0.f;

    const float* Kb = K_all   + (size_t)l * P_ * D_ + ldp;
    const float* xb = x_query + (size_t)l * D_ + ldp;

    float4 pk[7], px[2];
    #pragma unroll
    for (int j = 0; j < 7; ++j) {
        int p = lr + (j << 4);
        pk[j] = (p < P_) ? *(const float4*)(Kb + (size_t)p * D_)
                         : make_float4(0.f, 0.f, 0.f, 0.f);
    }
    #pragma unroll
    for (int i = 0; i < 2; ++i)
        px[i] = *(const float4*)(xb + (size_t)(b0 + lr + (i << 4)) * (L_ * D_));
    {
        float* Kc = pool;
        float* Xc = pool + PP * KPITCH;
        #pragma unroll
        for (int j = 0; j < 7; ++j) {
            float* r = &Kc[(lr + (j << 4)) * KPITCH + ldp];
            *(float2*)(r    ) = make_float2(pk[j].x, pk[j].y);
            *(float2*)(r + 2) = make_float2(pk[j].z, pk[j].w);
        }
        #pragma unroll
        for (int i = 0; i < 2; ++i) {
            float* r = &Xc[(lr + (i << 4)) * XPITCH + ldp];
            *(float2*)(r    ) = make_float2(px[i].x, px[i].y);
            *(float2*)(r + 2) = make_float2(px[i].z, px[i].w);
        }
    }
    __syncthreads();

    for (int c = 0; c < NCH; ++c) {
        const float* base = pool + (c & 1) * HALF;
        const float* Kc = base;
        const float* Xc = base + PP * KPITCH;

        if (c + 1 < NCH) {
            int d0 = (c + 1) * DC;
            #pragma unroll
            for (int j = 0; j < 7; ++j) {
                int p = lr + (j << 4);
                pk[j] = (p < P_) ? *(const float4*)(Kb + (size_t)p * D_ + d0)
                                 : make_float4(0.f, 0.f, 0.f, 0.f);
            }
            #pragma unroll
            for (int i = 0; i < 2; ++i)
                px[i] = *(const float4*)(xb + (size_t)(b0 + lr + (i << 4)) * (L_ * D_) + d0);
        }

        #pragma unroll 2
        for (int dd = 0; dd < DC; dd += 2) {
            float2 kv[7], xv[4];
            #pragma unroll
            for (int j = 0; j < 7; ++j) kv[j] = *(const float2*)&Kc[(tx + (j << 4)) * KPITCH + dd];
            #pragma unroll
            for (int i = 0; i < 4; ++i) xv[i] = *(const float2*)&Xc[(4 * ty + i) * XPITCH + dd];
            #pragma unroll
            for (int i = 0; i < 4; ++i)
                #pragma unroll
                for (int j = 0; j < 7; ++j) {
                    acc[i][j] = fmaf(xv[i].x, kv[j].x, acc[i][j]);
                    acc[i][j] = fmaf(xv[i].y, kv[j].y, acc[i][j]);
                }
        }

        if (c + 1 < NCH) {
            float* dst = pool + ((c + 1) & 1) * HALF;
            float* Kd = dst;
            float* Xd = dst + PP * KPITCH;
            #pragma unroll
            for (int j = 0; j < 7; ++j) {
                float* r = &Kd[(lr + (j << 4)) * KPITCH + ldp];
                *(float2*)(r    ) = make_float2(pk[j].x, pk[j].y);
                *(float2*)(r + 2) = make_float2(pk[j].z, pk[j].w);
            }
            #pragma unroll
            for (int i = 0; i < 2; ++i) {
                float* r = &Xd[(lr + (i << 4)) * XPITCH + ldp];
                *(float2*)(r    ) = make_float2(px[i].x, px[i].y);
                *(float2*)(r + 2) = make_float2(px[i].z, px[i].w);
            }
        }
        __syncthreads();
    }

    float* S = pool;   // [BT][128], aliases buffer 0

    #pragma unroll
    for (int j = 0; j < 8; ++j) {
        int p = tx + (j << 4);
        float ik = (p < P_) ? g_invK[l * P_ + p] : 0.f;
        #pragma unroll
        for (int i = 0; i < 4; ++i) {
            float v = (j < 7 && p < P_) ? acc[i][j] * ik : -FLT_MAX;
            S[(4 * ty + i) * 128 + p] = v;
        }
    }
    __syncthreads();

    const int w  = t >> 5;
    const int ln = t & 31;
    for (int bi = 0; bi < 8; ++bi) {
        int b = (w << 3) + bi;           // 0..31
        float v[4];
        #pragma unroll
        for (int j = 0; j < 4; ++j) v[j] = S[b * 128 + ln + (j << 5)];
        int base = (l * B_ + b0 + b) * TOPK;
        #pragma unroll
        for (int k = 0; k < TOPK; ++k) {
            float bv = v[0]; int bj = 0;
            #pragma unroll
            for (int j = 1; j < 4; ++j) if (v[j] > bv) { bv = v[j]; bj = j; }
            int bidx = ln + (bj << 5);
            #pragma unroll
            for (int o = 16; o; o >>= 1) {
                float ov = __shfl_xor_sync(0xffffffffu, bv, o);
                int   oi = __shfl_xor_sync(0xffffffffu, bidx, o);
                if (ov > bv || (ov == bv && oi < bidx)) { bv = ov; bidx = oi; }
            }
            if (ln == 0) {
                g_idx[base + k] = bidx;
                g_w  [base + k] = g_coef[l * P_ + bidx];
            }
            if ((bidx & 31) == ln) v[bidx >> 5] = -FLT_MAX;
        }
    }
}

// =====================================================================
// Kernel C: OUT[l,b,:] = sum_k w[l,b,k] * P_all[l, idx[l,b,k], :]
// R13: weights/indices packed into float4/int4 smem so each warp
// iteration issues 4 broadcast loads (2x LDS.128 + 2 scalar) instead of
// 10 scalar LDS — cuts l1tex wavefronts/iter 20 -> 14 (kernel was
// measured l1tex-wavefront-bound at 78.5% L1, 30.9% DRAM).
// =====================================================================
__global__ __launch_bounds__(256) void out_kernel(const float* __restrict__ P_all,
                                                  float* __restrict__ out) {
    const int l    = blockIdx.z;
    const int bt   = blockIdx.y;
    const int col0 = blockIdx.x * CC;

    __shared__ float Ps[P_][CC];        // 25.6 KB
    __shared__ __align__(16) float4 wq[BTC];   // w0..w3
    __shared__ __align__(16) int4   iq[BTC];   // i0..i3
    __shared__ float wl[BTC];                  // w4
    __shared__ int   il[BTC];                  // i4

    const int t = threadIdx.x;

    // stage packed weights/indices (128 threads active, 1 batch each)
    if (t < BTC) {
        int gi = (l * B_ + bt * BTC + t) * TOPK;
        wq[t] = make_float4(g_w[gi], g_w[gi + 1], g_w[gi + 2], g_w[gi + 3]);
        wl[t] = g_w[gi + 4];
        iq[t] = make_int4(g_idx[gi], g_idx[gi + 1], g_idx[gi + 2], g_idx[gi + 3]);
        il[t] = g_idx[gi + 4];
    }
    // stage P col-slice
    const float* Pl = P_all + (size_t)l * P_ * ROW_ + col0;
    for (int i = t; i < P_ * (CC / 2); i += 256) {
        int p = i >> 5, c = i & 31;
        float2 v = *(const float2*)(Pl + (size_t)p * ROW_ + 2 * c);
        *(float2*)&Ps[p][2 * c] = v;
    }
    __syncthreads();

    const int w  = t >> 5;
    const int ln = t & 31;
    float* ob = out + (size_t)(l * B_ + bt * BTC) * ROW_ + col0 + 2 * ln;
    #pragma unroll 4
    for (int bb = 0; bb < 16; ++bb) {
        int b = w * 16 + bb;
        float4 wv = wq[b];            // LDS.128 broadcast (1 wf)
        int4   iv = iq[b];            // LDS.128 broadcast (1 wf)
        float  w4 = wl[b];
        int    i4 = il[b];
        float2 p0 = *(const float2*)&Ps[iv.x][2 * ln];
        float2 p1 = *(const float2*)&Ps[iv.y][2 * ln];
        float2 p2 = *(const float2*)&Ps[iv.z][2 * ln];
        float2 p3 = *(const float2*)&Ps[iv.w][2 * ln];
        float2 p4 = *(const float2*)&Ps[i4  ][2 * ln];
        float2 o;
        o.x = fmaf(w4, p4.x, fmaf(wv.w, p3.x, fmaf(wv.z, p2.x, fmaf(wv.y, p1.x, wv.x * p0.x))));
        o.y = fmaf(w4, p4.y, fmaf(wv.w, p3.y, fmaf(wv.z, p2.y, fmaf(wv.y, p1.y, wv.x * p0.y))));
        *(float2*)(ob + (size_t)b * ROW_) = o;
    }
}

// =====================================================================
// Dummy launch at position 3: ncu captures launch position 4 (confirmed
// R9/R11/R12).  Order prep, score, phase, out -> profile lands on the
// NEW out_kernel to verify the wavefront model.
// =====================================================================
__global__ void phase_kernel() { g_sink = 1; }

// =====================================================================
extern "C" void kernel_launch(void* const* d_in, const int* in_sizes, int n_in,
                              void* d_out, int out_size) {
    const float* x_query = (const float*)d_in[0];  // [B, L, D]
    const float* K_all   = (const float*)d_in[1];  // [L, P, D]
    const float* A_all   = (const float*)d_in[2];  // [L, P, D]
    const float* P_all   = (const float*)d_in[3];  // [L, P, Lp, D]
    float* out = (float*)d_out;                    // [L, B, Lp, E]
    (void)in_sizes; (void)n_in; (void)out_size;

    prep_kernel<<<(L_ * P_ * 32 + 255) / 256, 256>>>(K_all, A_all);
    score_kernel<<<dim3(B_ / BT, L_), 128>>>(x_query, K_all);
    phase_kernel<<<1, 1>>>();
    out_kernel<<<dim3(ROW_ / CC, B_ / BTC, L_), 256>>>(P_all, out);
}

// round 14
// speedup vs baseline: 1.2918x; 1.1074x over previous
#include <cuda_runtime.h>
#include <math.h>
#include <float.h>
#include <stdint.h>

#define L_    12
#define P_    100
#define B_    1024
#define D_    768
#define LP_   8
#define ROW_  (LP_*D_)   // 6144
#define TOPK  5
#define PP    112        // padded P (7 groups of 16)
#define BT    32         // batch tile (scores)
#define DC    32         // d chunk
#define NCH   (D_/DC)    // 24 chunks
#define KPITCH 34        // even pitch -> conflict-free float2 (bank-pair = p%16)
#define XPITCH 34
#define HALF  (PP*KPITCH + BT*XPITCH)   // 4896 floats per buffer
#define CC    128        // col tile (output)
// dynamic smem layout for out_kernel (bytes)
#define PS_FLOATS   (P_*CC)                       // 12800
#define SM_PS       0
#define SM_WQ       (PS_FLOATS*4)                 // 51200, 16B aligned
#define SM_IQ       (SM_WQ + B_*16)               // +16384
#define SM_WL       (SM_IQ + B_*16)               // +16384
#define SM_IL       (SM_WL + B_*4)                // +4096
#define SMEM_OUT    (SM_IL + B_*4)                // 92160 bytes

// ---- device scratch (no allocations allowed) ----
__device__ float  g_invK[L_*P_];
__device__ float  g_coef[L_*P_];
__device__ float4 g_wq [L_*B_];    // w0..w3 packed
__device__ int4   g_iq [L_*B_];    // i0..i3 packed
__device__ float  g_wl [L_*B_];    // w4
__device__ int    g_il [L_*B_];    // i4
__device__ int    g_sink;

// =====================================================================
// Kernel A: one warp per (l,p): invK and coef = dot(l2norm(K),l2norm(A))
// =====================================================================
__global__ __launch_bounds__(256) void prep_kernel(const float* __restrict__ K_all,
                                                   const float* __restrict__ A_all) {
    int gw = (blockIdx.x * 256 + threadIdx.x) >> 5;   // 0..1199
    int ln = threadIdx.x & 31;
    if (gw >= L_ * P_) return;
    const float* Kr = K_all + (size_t)gw * D_;
    const float* Ar = A_all + (size_t)gw * D_;
    float kk = 0.f, aa = 0.f, ka = 0.f;
    #pragma unroll
    for (int i = 0; i < 6; ++i) {
        float4 k = *(const float4*)(Kr + ((i << 5) + ln) * 4);
        float4 a = *(const float4*)(Ar + ((i << 5) + ln) * 4);
        kk = fmaf(k.x,k.x, fmaf(k.y,k.y, fmaf(k.z,k.z, fmaf(k.w,k.w, kk))));
        aa = fmaf(a.x,a.x, fmaf(a.y,a.y, fmaf(a.z,a.z, fmaf(a.w,a.w, aa))));
        ka = fmaf(k.x,a.x, fmaf(k.y,a.y, fmaf(k.z,a.z, fmaf(k.w,a.w, ka))));
    }
    #pragma unroll
    for (int o = 16; o; o >>= 1) {
        kk += __shfl_xor_sync(0xffffffffu, kk, o);
        aa += __shfl_xor_sync(0xffffffffu, aa, o);
        ka += __shfl_xor_sync(0xffffffffu, ka, o);
    }
    if (ln == 0) {
        float ik = 1.f / fmaxf(sqrtf(kk), 1e-12f);
        float ia = 1.f / fmaxf(sqrtf(aa), 1e-12f);
        g_invK[gw] = ik;
        g_coef[gw] = ka * ik * ia;
    }
}

// =====================================================================
// Kernel B: scores GEMM (fp32) + top-5.  Block = (l, 32 batches), 128 thr.
// Double-buffered smem staging with register prefetch (R12 win).
// Lane 0 accumulates the 5 (w, idx) in registers and writes PACKED
// float4/int4 outputs for coalesced staging in out_kernel.
// =====================================================================
__global__ __launch_bounds__(128) void score_kernel(const float* __restrict__ x_query,
                                                    const float* __restrict__ K_all) {
    const int l  = blockIdx.y;
    const int b0 = blockIdx.x * BT;

    __shared__ __align__(16) float pool[2 * HALF];   // 39.2 KB

    const int t   = threadIdx.x;
    const int tx  = t & 15;          // p group
    const int ty  = t >> 4;          // 0..7 -> batches 4ty..4ty+3
    const int ldp = (t & 7) << 2;    // loader d offset 0..28
    const int lr  = t >> 3;          // loader row 0..15

    float acc[4][7];
    #pragma unroll
    for (int i = 0; i < 4; ++i)
        #pragma unroll
        for (int j = 0; j < 7; ++j) acc[i][j] = 0.f;

    const float* Kb = K_all   + (size_t)l * P_ * D_ + ldp;
    const float* xb = x_query + (size_t)l * D_ + ldp;

    float4 pk[7], px[2];
    #pragma unroll
    for (int j = 0; j < 7; ++j) {
        int p = lr + (j << 4);
        pk[j] = (p < P_) ? *(const float4*)(Kb + (size_t)p * D_)
                         : make_float4(0.f, 0.f, 0.f, 0.f);
    }
    #pragma unroll
    for (int i = 0; i < 2; ++i)
        px[i] = *(const float4*)(xb + (size_t)(b0 + lr + (i << 4)) * (L_ * D_));
    {
        float* Kc = pool;
        float* Xc = pool + PP * KPITCH;
        #pragma unroll
        for (int j = 0; j < 7; ++j) {
            float* r = &Kc[(lr + (j << 4)) * KPITCH + ldp];
            *(float2*)(r    ) = make_float2(pk[j].x, pk[j].y);
            *(float2*)(r + 2) = make_float2(pk[j].z, pk[j].w);
        }
        #pragma unroll
        for (int i = 0; i < 2; ++i) {
            float* r = &Xc[(lr + (i << 4)) * XPITCH + ldp];
            *(float2*)(r    ) = make_float2(px[i].x, px[i].y);
            *(float2*)(r + 2) = make_float2(px[i].z, px[i].w);
        }
    }
    __syncthreads();

    for (int c = 0; c < NCH; ++c) {
        const float* base = pool + (c & 1) * HALF;
        const float* Kc = base;
        const float* Xc = base + PP * KPITCH;

        if (c + 1 < NCH) {
            int d0 = (c + 1) * DC;
            #pragma unroll
            for (int j = 0; j < 7; ++j) {
                int p = lr + (j << 4);
                pk[j] = (p < P_) ? *(const float4*)(Kb + (size_t)p * D_ + d0)
                                 : make_float4(0.f, 0.f, 0.f, 0.f);
            }
            #pragma unroll
            for (int i = 0; i < 2; ++i)
                px[i] = *(const float4*)(xb + (size_t)(b0 + lr + (i << 4)) * (L_ * D_) + d0);
        }

        #pragma unroll 2
        for (int dd = 0; dd < DC; dd += 2) {
            float2 kv[7], xv[4];
            #pragma unroll
            for (int j = 0; j < 7; ++j) kv[j] = *(const float2*)&Kc[(tx + (j << 4)) * KPITCH + dd];
            #pragma unroll
            for (int i = 0; i < 4; ++i) xv[i] = *(const float2*)&Xc[(4 * ty + i) * XPITCH + dd];
            #pragma unroll
            for (int i = 0; i < 4; ++i)
                #pragma unroll
                for (int j = 0; j < 7; ++j) {
                    acc[i][j] = fmaf(xv[i].x, kv[j].x, acc[i][j]);
                    acc[i][j] = fmaf(xv[i].y, kv[j].y, acc[i][j]);
                }
        }

        if (c + 1 < NCH) {
            float* dst = pool + ((c + 1) & 1) * HALF;
            float* Kd = dst;
            float* Xd = dst + PP * KPITCH;
            #pragma unroll
            for (int j = 0; j < 7; ++j) {
                float* r = &Kd[(lr + (j << 4)) * KPITCH + ldp];
                *(float2*)(r    ) = make_float2(pk[j].x, pk[j].y);
                *(float2*)(r + 2) = make_float2(pk[j].z, pk[j].w);
            }
            #pragma unroll
            for (int i = 0; i < 2; ++i) {
                float* r = &Xd[(lr + (i << 4)) * XPITCH + ldp];
                *(float2*)(r    ) = make_float2(px[i].x, px[i].y);
                *(float2*)(r + 2) = make_float2(px[i].z, px[i].w);
            }
        }
        __syncthreads();
    }

    float* S = pool;   // [BT][128], aliases buffer 0

    #pragma unroll
    for (int j = 0; j < 8; ++j) {
        int p = tx + (j << 4);
        float ik = (p < P_) ? g_invK[l * P_ + p] : 0.f;
        #pragma unroll
        for (int i = 0; i < 4; ++i) {
            float v = (j < 7 && p < P_) ? acc[i][j] * ik : -FLT_MAX;
            S[(4 * ty + i) * 128 + p] = v;
        }
    }
    __syncthreads();

    const int w  = t >> 5;
    const int ln = t & 31;
    for (int bi = 0; bi < 8; ++bi) {
        int b = (w << 3) + bi;           // 0..31
        float v[4];
        #pragma unroll
        for (int j = 0; j < 4; ++j) v[j] = S[b * 128 + ln + (j << 5)];
        float wv[TOPK]; int iv[TOPK];
        #pragma unroll
        for (int k = 0; k < TOPK; ++k) {
            float bv = v[0]; int bj = 0;
            #pragma unroll
            for (int j = 1; j < 4; ++j) if (v[j] > bv) { bv = v[j]; bj = j; }
            int bidx = ln + (bj << 5);
            #pragma unroll
            for (int o = 16; o; o >>= 1) {
                float ov = __shfl_xor_sync(0xffffffffu, bv, o);
                int   oi = __shfl_xor_sync(0xffffffffu, bidx, o);
                if (ov > bv || (ov == bv && oi < bidx)) { bv = ov; bidx = oi; }
            }
            wv[k] = g_coef[l * P_ + bidx];   // only lane 0's value is used
            iv[k] = bidx;
            if ((bidx & 31) == ln) v[bidx >> 5] = -FLT_MAX;
        }
        if (ln == 0) {
            int gb = l * B_ + b0 + b;
            g_wq[gb] = make_float4(wv[0], wv[1], wv[2], wv[3]);
            g_iq[gb] = make_int4 (iv[0], iv[1], iv[2], iv[3]);
            g_wl[gb] = wv[4];
            g_il[gb] = iv[4];
        }
    }
}

// =====================================================================
// Kernel C: OUT[l,b,:] = sum_k w[l,b,k] * P_all[l, idx[l,b,k], :]
// R14: block = (l, coltile 128) serving ALL 1024 batches -> P col-slice
// staged ONCE per block (LDG+STS traffic /8), gather via LDS.128.
// 92 KB dynamic smem, 2 blocks/SM, grid 48x12 = 576 blocks.
// =====================================================================
__global__ __launch_bounds__(256) void out_kernel(const float* __restrict__ P_all,
                                                  float* __restrict__ out) {
    extern __shared__ __align__(16) char smem[];
    float*  Ps = (float*) (smem + SM_PS);    // [P_][CC]
    float4* wq = (float4*)(smem + SM_WQ);    // [B_]
    int4*   iq = (int4*)  (smem + SM_IQ);    // [B_]
    float*  wl = (float*) (smem + SM_WL);    // [B_]
    int*    il = (int*)   (smem + SM_IL);    // [B_]

    const int l    = blockIdx.y;
    const int col0 = blockIdx.x * CC;
    const int t    = threadIdx.x;

    // stage ALL batches' packed weights/indices (coalesced LDG.128)
    for (int i = t; i < B_; i += 256) {
        int gb = l * B_ + i;
        wq[i] = g_wq[gb];
        iq[i] = g_iq[gb];
        wl[i] = g_wl[gb];
        il[i] = g_il[gb];
    }
    // stage P col-slice once: 100 rows x 128 cols (float4 loads/stores)
    const float* Pl = P_all + (size_t)l * P_ * ROW_ + col0;
    for (int i = t; i < P_ * (CC / 4); i += 256) {
        int p = i >> 5, c = i & 31;              // 32 float4 per row
        float4 v = *(const float4*)(Pl + (size_t)p * ROW_ + 4 * c);
        *(float4*)&Ps[p * CC + 4 * c] = v;
    }
    __syncthreads();

    const int w  = t >> 5;
    const int ln = t & 31;
    float* ob = out + (size_t)l * B_ * ROW_ + col0 + 4 * ln;
    for (int b = w; b < B_; b += 8) {
        float4 wv = wq[b];                       // LDS.128 broadcast
        int4   ivv = iq[b];                      // LDS.128 broadcast
        float  w4 = wl[b];
        int    i4 = il[b];
        float4 p0 = *(const float4*)&Ps[ivv.x * CC + 4 * ln];
        float4 p1 = *(const float4*)&Ps[ivv.y * CC + 4 * ln];
        float4 p2 = *(const float4*)&Ps[ivv.z * CC + 4 * ln];
        float4 p3 = *(const float4*)&Ps[ivv.w * CC + 4 * ln];
        float4 p4 = *(const float4*)&Ps[i4    * CC + 4 * ln];
        float4 o;
        o.x = fmaf(w4, p4.x, fmaf(wv.w, p3.x, fmaf(wv.z, p2.x, fmaf(wv.y, p1.x, wv.x * p0.x))));
        o.y = fmaf(w4, p4.y, fmaf(wv.w, p3.y, fmaf(wv.z, p2.y, fmaf(wv.y, p1.y, wv.x * p0.y))));
        o.z = fmaf(w4, p4.z, fmaf(wv.w, p3.z, fmaf(wv.z, p2.z, fmaf(wv.y, p1.z, wv.x * p0.z))));
        o.w = fmaf(w4, p4.w, fmaf(wv.w, p3.w, fmaf(wv.z, p2.w, fmaf(wv.y, p1.w, wv.x * p0.w))));
        *(float4*)(ob + (size_t)b * ROW_) = o;
    }
}

// =====================================================================
// Dummy launch at position 3: ncu captures launch position 4 (confirmed
// R9/R11/R12/R13).  Order prep, score, phase, out -> profile lands on
// the NEW out_kernel.
// =====================================================================
__global__ void phase_kernel() { g_sink = 1; }

// =====================================================================
extern "C" void kernel_launch(void* const* d_in, const int* in_sizes, int n_in,
                              void* d_out, int out_size) {
    const float* x_query = (const float*)d_in[0];  // [B, L, D]
    const float* K_all   = (const float*)d_in[1];  // [L, P, D]
    const float* A_all   = (const float*)d_in[2];  // [L, P, D]
    const float* P_all   = (const float*)d_in[3];  // [L, P, Lp, D]
    float* out = (float*)d_out;                    // [L, B, Lp, E]
    (void)in_sizes; (void)n_in; (void)out_size;

    cudaFuncSetAttribute(out_kernel, cudaFuncAttributeMaxDynamicSharedMemorySize, SMEM_OUT);

    prep_kernel<<<(L_ * P_ * 32 + 255) / 256, 256>>>(K_all, A_all);
    score_kernel<<<dim3(B_ / BT, L_), 128>>>(x_query, K_all);
    phase_kernel<<<1, 1>>>();
    out_kernel<<<dim3(ROW_ / CC, L_), 256, SMEM_OUT>>>(P_all, out);
}

// round 15
// speedup vs baseline: 1.3725x; 1.0625x over previous
#include <cuda_runtime.h>
#include <math.h>
#include <float.h>
#include <stdint.h>

#define L_    12
#define P_    100
#define B_    1024
#define D_    768
#define LP_   8
#define ROW_  (LP_*D_)   // 6144
#define TOPK  5
#define PP    112        // padded P (7 groups of 16)
#define BT    32         // batch tile (scores)
#define DC    32         // d chunk
#define NCH   (D_/DC)    // 24 chunks
#define KPITCH 34        // even pitch -> conflict-free float2 (bank-pair = p%16)
#define XPITCH 34
#define HALF  (PP*KPITCH + BT*XPITCH)   // 4896 floats per buffer
#define CC    128        // col tile (output)
#define OTHR  512        // out_kernel threads (R15: 256 -> 512 for occupancy)
// dynamic smem layout for out_kernel (bytes)
#define PS_FLOATS   (P_*CC)                       // 12800
#define SM_PS       0
#define SM_WQ       (PS_FLOATS*4)                 // 51200, 16B aligned
#define SM_IQ       (SM_WQ + B_*16)               // +16384
#define SM_WL       (SM_IQ + B_*16)               // +16384
#define SM_IL       (SM_WL + B_*4)                // +4096
#define SMEM_OUT    (SM_IL + B_*4)                // 92160 bytes

// ---- device scratch (no allocations allowed) ----
__device__ float  g_invK[L_*P_];
__device__ float  g_coef[L_*P_];
__device__ float4 g_wq [L_*B_];    // w0..w3 packed
__device__ int4   g_iq [L_*B_];    // i0..i3 packed
__device__ float  g_wl [L_*B_];    // w4
__device__ int    g_il [L_*B_];    // i4
__device__ int    g_sink;

// =====================================================================
// Kernel A: one warp per (l,p): invK and coef = dot(l2norm(K),l2norm(A))
// =====================================================================
__global__ __launch_bounds__(256) void prep_kernel(const float* __restrict__ K_all,
                                                   const float* __restrict__ A_all) {
    int gw = (blockIdx.x * 256 + threadIdx.x) >> 5;   // 0..1199
    int ln = threadIdx.x & 31;
    if (gw >= L_ * P_) return;
    const float* Kr = K_all + (size_t)gw * D_;
    const float* Ar = A_all + (size_t)gw * D_;
    float kk = 0.f, aa = 0.f, ka = 0.f;
    #pragma unroll
    for (int i = 0; i < 6; ++i) {
        float4 k = *(const float4*)(Kr + ((i << 5) + ln) * 4);
        float4 a = *(const float4*)(Ar + ((i << 5) + ln) * 4);
        kk = fmaf(k.x,k.x, fmaf(k.y,k.y, fmaf(k.z,k.z, fmaf(k.w,k.w, kk))));
        aa = fmaf(a.x,a.x, fmaf(a.y,a.y, fmaf(a.z,a.z, fmaf(a.w,a.w, aa))));
        ka = fmaf(k.x,a.x, fmaf(k.y,a.y, fmaf(k.z,a.z, fmaf(k.w,a.w, ka))));
    }
    #pragma unroll
    for (int o = 16; o; o >>= 1) {
        kk += __shfl_xor_sync(0xffffffffu, kk, o);
        aa += __shfl_xor_sync(0xffffffffu, aa, o);
        ka += __shfl_xor_sync(0xffffffffu, ka, o);
    }
    if (ln == 0) {
        float ik = 1.f / fmaxf(sqrtf(kk), 1e-12f);
        float ia = 1.f / fmaxf(sqrtf(aa), 1e-12f);
        g_invK[gw] = ik;
        g_coef[gw] = ka * ik * ia;
    }
}

// =====================================================================
// Kernel B: scores GEMM (fp32) + top-5.  Block = (l, 32 batches), 128 thr.
// Double-buffered smem staging with register prefetch (R12 win).
// Lane 0 accumulates the 5 (w, idx) in registers and writes PACKED
// float4/int4 outputs for coalesced staging in out_kernel.
// =====================================================================
__global__ __launch_bounds__(128) void score_kernel(const float* __restrict__ x_query,
                                                    const float* __restrict__ K_all) {
    const int l  = blockIdx.y;
    const int b0 = blockIdx.x * BT;

    __shared__ __align__(16) float pool[2 * HALF];   // 39.2 KB

    const int t   = threadIdx.x;
    const int tx  = t & 15;          // p group
    const int ty  = t >> 4;          // 0..7 -> batches 4ty..4ty+3
    const int ldp = (t & 7) << 2;    // loader d offset 0..28
    const int lr  = t >> 3;          // loader row 0..15

    float acc[4][7];
    #pragma unroll
    for (int i = 0; i < 4; ++i)
        #pragma unroll
        for (int j = 0; j < 7; ++j) acc[i][j] = 0.f;

    const float* Kb = K_all   + (size_t)l * P_ * D_ + ldp;
    const float* xb = x_query + (size_t)l * D_ + ldp;

    float4 pk[7], px[2];
    #pragma unroll
    for (int j = 0; j < 7; ++j) {
        int p = lr + (j << 4);
        pk[j] = (p < P_) ? *(const float4*)(Kb + (size_t)p * D_)
                         : make_float4(0.f, 0.f, 0.f, 0.f);
    }
    #pragma unroll
    for (int i = 0; i < 2; ++i)
        px[i] = *(const float4*)(xb + (size_t)(b0 + lr + (i << 4)) * (L_ * D_));
    {
        float* Kc = pool;
        float* Xc = pool + PP * KPITCH;
        #pragma unroll
        for (int j = 0; j < 7; ++j) {
            float* r = &Kc[(lr + (j << 4)) * KPITCH + ldp];
            *(float2*)(r    ) = make_float2(pk[j].x, pk[j].y);
            *(float2*)(r + 2) = make_float2(pk[j].z, pk[j].w);
        }
        #pragma unroll
        for (int i = 0; i < 2; ++i) {
            float* r = &Xc[(lr + (i << 4)) * XPITCH + ldp];
            *(float2*)(r    ) = make_float2(px[i].x, px[i].y);
            *(float2*)(r + 2) = make_float2(px[i].z, px[i].w);
        }
    }
    __syncthreads();

    for (int c = 0; c < NCH; ++c) {
        const float* base = pool + (c & 1) * HALF;
        const float* Kc = base;
        const float* Xc = base + PP * KPITCH;

        if (c + 1 < NCH) {
            int d0 = (c + 1) * DC;
            #pragma unroll
            for (int j = 0; j < 7; ++j) {
                int p = lr + (j << 4);
                pk[j] = (p < P_) ? *(const float4*)(Kb + (size_t)p * D_ + d0)
                                 : make_float4(0.f, 0.f, 0.f, 0.f);
            }
            #pragma unroll
            for (int i = 0; i < 2; ++i)
                px[i] = *(const float4*)(xb + (size_t)(b0 + lr + (i << 4)) * (L_ * D_) + d0);
        }

        #pragma unroll 2
        for (int dd = 0; dd < DC; dd += 2) {
            float2 kv[7], xv[4];
            #pragma unroll
            for (int j = 0; j < 7; ++j) kv[j] = *(const float2*)&Kc[(tx + (j << 4)) * KPITCH + dd];
            #pragma unroll
            for (int i = 0; i < 4; ++i) xv[i] = *(const float2*)&Xc[(4 * ty + i) * XPITCH + dd];
            #pragma unroll
            for (int i = 0; i < 4; ++i)
                #pragma unroll
                for (int j = 0; j < 7; ++j) {
                    acc[i][j] = fmaf(xv[i].x, kv[j].x, acc[i][j]);
                    acc[i][j] = fmaf(xv[i].y, kv[j].y, acc[i][j]);
                }
        }

        if (c + 1 < NCH) {
            float* dst = pool + ((c + 1) & 1) * HALF;
            float* Kd = dst;
            float* Xd = dst + PP * KPITCH;
            #pragma unroll
            for (int j = 0; j < 7; ++j) {
                float* r = &Kd[(lr + (j << 4)) * KPITCH + ldp];
                *(float2*)(r    ) = make_float2(pk[j].x, pk[j].y);
                *(float2*)(r + 2) = make_float2(pk[j].z, pk[j].w);
            }
            #pragma unroll
            for (int i = 0; i < 2; ++i) {
                float* r = &Xd[(lr + (i << 4)) * XPITCH + ldp];
                *(float2*)(r    ) = make_float2(px[i].x, px[i].y);
                *(float2*)(r + 2) = make_float2(px[i].z, px[i].w);
            }
        }
        __syncthreads();
    }

    float* S = pool;   // [BT][128], aliases buffer 0

    #pragma unroll
    for (int j = 0; j < 8; ++j) {
        int p = tx + (j << 4);
        float ik = (p < P_) ? g_invK[l * P_ + p] : 0.f;
        #pragma unroll
        for (int i = 0; i < 4; ++i) {
            float v = (j < 7 && p < P_) ? acc[i][j] * ik : -FLT_MAX;
            S[(4 * ty + i) * 128 + p] = v;
        }
    }
    __syncthreads();

    const int w  = t >> 5;
    const int ln = t & 31;
    for (int bi = 0; bi < 8; ++bi) {
        int b = (w << 3) + bi;           // 0..31
        float v[4];
        #pragma unroll
        for (int j = 0; j < 4; ++j) v[j] = S[b * 128 + ln + (j << 5)];
        float wv[TOPK]; int iv[TOPK];
        #pragma unroll
        for (int k = 0; k < TOPK; ++k) {
            float bv = v[0]; int bj = 0;
            #pragma unroll
            for (int j = 1; j < 4; ++j) if (v[j] > bv) { bv = v[j]; bj = j; }
            int bidx = ln + (bj << 5);
            #pragma unroll
            for (int o = 16; o; o >>= 1) {
                float ov = __shfl_xor_sync(0xffffffffu, bv, o);
                int   oi = __shfl_xor_sync(0xffffffffu, bidx, o);
                if (ov > bv || (ov == bv && oi < bidx)) { bv = ov; bidx = oi; }
            }
            wv[k] = g_coef[l * P_ + bidx];   // only lane 0's value is used
            iv[k] = bidx;
            if ((bidx & 31) == ln) v[bidx >> 5] = -FLT_MAX;
        }
        if (ln == 0) {
            int gb = l * B_ + b0 + b;
            g_wq[gb] = make_float4(wv[0], wv[1], wv[2], wv[3]);
            g_iq[gb] = make_int4 (iv[0], iv[1], iv[2], iv[3]);
            g_wl[gb] = wv[4];
            g_il[gb] = iv[4];
        }
    }
}

// =====================================================================
// Kernel C: OUT[l,b,:] = sum_k w[l,b,k] * P_all[l, idx[l,b,k], :]
// Block = (l, coltile 128) serving ALL 1024 batches; P col-slice staged
// once per block.  R15: 512 threads (was 256) -> 32 warps/SM at the
// same 92 KB smem / 2 blocks/SM, doubling latency-hiding (measured
// occ=24.7%, issue=25.4% at 256 thr).
// =====================================================================
__global__ __launch_bounds__(OTHR) void out_kernel(const float* __restrict__ P_all,
                                                   float* __restrict__ out) {
    extern __shared__ __align__(16) char smem[];
    float*  Ps = (float*) (smem + SM_PS);    // [P_][CC]
    float4* wq = (float4*)(smem + SM_WQ);    // [B_]
    int4*   iq = (int4*)  (smem + SM_IQ);    // [B_]
    float*  wl = (float*) (smem + SM_WL);    // [B_]
    int*    il = (int*)   (smem + SM_IL);    // [B_]

    const int l    = blockIdx.y;
    const int col0 = blockIdx.x * CC;
    const int t    = threadIdx.x;

    // stage ALL batches' packed weights/indices (coalesced LDG.128)
    for (int i = t; i < B_; i += OTHR) {
        int gb = l * B_ + i;
        wq[i] = g_wq[gb];
        iq[i] = g_iq[gb];
        wl[i] = g_wl[gb];
        il[i] = g_il[gb];
    }
    // stage P col-slice once: 100 rows x 128 cols (float4 loads/stores)
    const float* Pl = P_all + (size_t)l * P_ * ROW_ + col0;
    for (int i = t; i < P_ * (CC / 4); i += OTHR) {
        int p = i >> 5, c = i & 31;              // 32 float4 per row
        float4 v = *(const float4*)(Pl + (size_t)p * ROW_ + 4 * c);
        *(float4*)&Ps[p * CC + 4 * c] = v;
    }
    __syncthreads();

    const int w  = t >> 5;                       // 0..15
    const int ln = t & 31;
    float* ob = out + (size_t)l * B_ * ROW_ + col0 + 4 * ln;
    for (int b = w; b < B_; b += OTHR / 32) {
        float4 wv = wq[b];                       // LDS.128 broadcast
        int4   ivv = iq[b];                      // LDS.128 broadcast
        float  w4 = wl[b];
        int    i4 = il[b];
        float4 p0 = *(const float4*)&Ps[ivv.x * CC + 4 * ln];
        float4 p1 = *(const float4*)&Ps[ivv.y * CC + 4 * ln];
        float4 p2 = *(const float4*)&Ps[ivv.z * CC + 4 * ln];
        float4 p3 = *(const float4*)&Ps[ivv.w * CC + 4 * ln];
        float4 p4 = *(const float4*)&Ps[i4    * CC + 4 * ln];
        float4 o;
        o.x = fmaf(w4, p4.x, fmaf(wv.w, p3.x, fmaf(wv.z, p2.x, fmaf(wv.y, p1.x, wv.x * p0.x))));
        o.y = fmaf(w4, p4.y, fmaf(wv.w, p3.y, fmaf(wv.z, p2.y, fmaf(wv.y, p1.y, wv.x * p0.y))));
        o.z = fmaf(w4, p4.z, fmaf(wv.w, p3.z, fmaf(wv.z, p2.z, fmaf(wv.y, p1.z, wv.x * p0.z))));
        o.w = fmaf(w4, p4.w, fmaf(wv.w, p3.w, fmaf(wv.z, p2.w, fmaf(wv.y, p1.w, wv.x * p0.w))));
        *(float4*)(ob + (size_t)b * ROW_) = o;
    }
}

// =====================================================================
// Dummy launch at position 3: ncu captures launch position 4 (confirmed
// R9/R11-R14).  Order prep, score, phase, out -> profile lands on the
// NEW out_kernel.
// =====================================================================
__global__ void phase_kernel() { g_sink = 1; }

// =====================================================================
extern "C" void kernel_launch(void* const* d_in, const int* in_sizes, int n_in,
                              void* d_out, int out_size) {
    const float* x_query = (const float*)d_in[0];  // [B, L, D]
    const float* K_all   = (const float*)d_in[1];  // [L, P, D]
    const float* A_all   = (const float*)d_in[2];  // [L, P, D]
    const float* P_all   = (const float*)d_in[3];  // [L, P, Lp, D]
    float* out = (float*)d_out;                    // [L, B, Lp, E]
    (void)in_sizes; (void)n_in; (void)out_size;

    cudaFuncSetAttribute(out_kernel, cudaFuncAttributeMaxDynamicSharedMemorySize, SMEM_OUT);

    prep_kernel<<<(L_ * P_ * 32 + 255) / 256, 256>>>(K_all, A_all);
    score_kernel<<<dim3(B_ / BT, L_), 128>>>(x_query, K_all);
    phase_kernel<<<1, 1>>>();
    out_kernel<<<dim3(ROW_ / CC, L_), OTHR, SMEM_OUT>>>(P_all, out);
}